// round 6
// baseline (speedup 1.0000x reference)
#include <cuda_runtime.h>
#include <cstdint>

#define NB 2
#define NS 2048
#define ND 1024
#define NH 16
#define NHD 64

// Scratch: projected Q (pre-scaled by 0.125*log2e) and K, plus 1/(16*rowsum).
__device__ float g_Q[NB * NH * NS * NHD];     // [bh, s, hd]
__device__ float g_K[NB * NH * NS * NHD];     // [bh, s, hd]
__device__ float g_Linv[NB * NH * NS];        // [bh, q]

// ---------------------------------------------------------------------------
__device__ __forceinline__ uint32_t smem_u32(const void* p) {
    uint32_t a;
    asm("{ .reg .u64 t; cvta.to.shared.u64 t, %1; cvt.u32.u64 %0, t; }"
        : "=r"(a) : "l"(p));
    return a;
}
__device__ __forceinline__ void cp16(uint32_t s, const void* g) {
    asm volatile("cp.async.cg.shared.global [%0], [%1], 16;" :: "r"(s), "l"(g));
}
#define CP_COMMIT() asm volatile("cp.async.commit_group;" ::: "memory")
#define CP_WAIT1()  asm volatile("cp.async.wait_group 1;" ::: "memory")

__device__ __forceinline__ float ex2a(float x) {
    float y;
    asm("ex2.approx.f32 %0, %1;" : "=f"(y) : "f"(x));
    return y;
}

#define MMA_TF32(d, a, b0, b1)                                                 \
    asm volatile(                                                              \
        "mma.sync.aligned.m16n8k8.row.col.f32.tf32.tf32.f32 "                  \
        "{%0,%1,%2,%3}, {%4,%5,%6,%7}, {%8,%9}, {%0,%1,%2,%3};"                \
        : "+f"((d)[0]), "+f"((d)[1]), "+f"((d)[2]), "+f"((d)[3])               \
        : "r"((a)[0]), "r"((a)[1]), "r"((a)[2]), "r"((a)[3]),                  \
          "r"(b0), "r"(b1))

// Q scale folds 1/sqrt(64) and log2(e) so softmax uses raw 2^x.
#define QSCALE 0.18033688011112042f

// ---------------------------------------------------------------------------
// Projection GEMM (fused Q & K via blockIdx.z), mma.sync tf32.
//   BM=256, BN=128, BK=32, double-buffered cp.async.
//   8 warps as 4(m) x 2(n); warp tile 64x64.
// ---------------------------------------------------------------------------
#define PJ_STRIDE 36
#define PJ_XBUF (256 * PJ_STRIDE)
#define PJ_WBUF (128 * PJ_STRIDE)
#define PJ_SMEM_TOTAL ((2 * PJ_XBUF + 2 * PJ_WBUF) * 4)   // 110,592 B

__global__ __launch_bounds__(256) void proj_kernel(
    const float* __restrict__ q_in, const float* __restrict__ k_in,
    const float* __restrict__ Wq, const float* __restrict__ bq,
    const float* __restrict__ Wk, const float* __restrict__ bk)
{
    const int z = blockIdx.z;
    const float* __restrict__ X = z ? k_in : q_in;
    const float* __restrict__ W = z ? Wk : Wq;
    const float* __restrict__ bias = z ? bk : bq;
    const float scale = z ? 1.0f : QSCALE;
    float* __restrict__ Out = z ? g_K : g_Q;

    extern __shared__ float pjs[];
    float* Xs = pjs;                       // [2][256][36]
    float* Ws = pjs + 2 * PJ_XBUF;         // [2][128][36]
    const uint32_t sb_x = smem_u32(Xs);
    const uint32_t sb_w = smem_u32(Ws);

    const int tid = threadIdx.x;
    const int lane = tid & 31, wid = tid >> 5;
    const int lq = lane & 3, lg = lane >> 2;
    const int wm = wid >> 1, wn = wid & 1;
    const int n0 = blockIdx.x * 128, m0 = blockIdx.y * 256;

    // X slab: 256 rows x 32 floats, 1 thread/row (8 cp16).
    // W slab: 128 rows x 32 floats, 2 threads/row (4 cp16).
    auto prefetch = [&](int st, int kb) {
        uint32_t xs = sb_x + (uint32_t)((st * PJ_XBUF + tid * PJ_STRIDE) * 4);
        const float* xg = X + (size_t)(m0 + tid) * ND + kb;
#pragma unroll
        for (int i = 0; i < 8; i++) cp16(xs + i * 16, xg + i * 4);
        int wr = tid >> 1, wc = (tid & 1) * 16;
        uint32_t ws = sb_w + (uint32_t)((st * PJ_WBUF + wr * PJ_STRIDE + wc) * 4);
        const float* wg = W + (size_t)(n0 + wr) * ND + kb + wc;
#pragma unroll
        for (int i = 0; i < 4; i++) cp16(ws + i * 16, wg + i * 4);
    };

    float acc[4][8][4];
#pragma unroll
    for (int mt = 0; mt < 4; mt++)
#pragma unroll
        for (int nt = 0; nt < 8; nt++)
#pragma unroll
            for (int j = 0; j < 4; j++) acc[mt][nt][j] = 0.0f;

    prefetch(0, 0);
    CP_COMMIT();

    for (int kb = 0; kb < ND / 32; kb++) {
        if (kb + 1 < ND / 32) prefetch((kb + 1) & 1, (kb + 1) * 32);
        CP_COMMIT();
        CP_WAIT1();
        __syncthreads();

        const float* Xb = Xs + (kb & 1) * PJ_XBUF;
        const float* Wb = Ws + (kb & 1) * PJ_WBUF;
#pragma unroll
        for (int s = 0; s < 4; s++) {
            uint32_t a[4][4];
#pragma unroll
            for (int mt = 0; mt < 4; mt++) {
                int r0 = wm * 64 + mt * 16 + lg;
                a[mt][0] = __float_as_uint(Xb[r0 * PJ_STRIDE + s * 8 + lq]);
                a[mt][1] = __float_as_uint(Xb[(r0 + 8) * PJ_STRIDE + s * 8 + lq]);
                a[mt][2] = __float_as_uint(Xb[r0 * PJ_STRIDE + s * 8 + lq + 4]);
                a[mt][3] = __float_as_uint(Xb[(r0 + 8) * PJ_STRIDE + s * 8 + lq + 4]);
            }
#pragma unroll
            for (int nt = 0; nt < 8; nt++) {
                int col = wn * 64 + nt * 8 + lg;
                uint32_t b0 = __float_as_uint(Wb[col * PJ_STRIDE + s * 8 + lq]);
                uint32_t b1 = __float_as_uint(Wb[col * PJ_STRIDE + s * 8 + lq + 4]);
#pragma unroll
                for (int mt = 0; mt < 4; mt++)
                    MMA_TF32(acc[mt][nt], a[mt], b0, b1);
            }
        }
        __syncthreads();
    }

    // Epilogue: bias + scale, scatter to [bh, s, hd]
#pragma unroll
    for (int mt = 0; mt < 4; mt++) {
        int m_lo = m0 + wm * 64 + mt * 16 + lg;
        int b_lo = m_lo >> 11, s_lo = m_lo & 2047;
        int m_hi = m_lo + 8;
        int b_hi = m_hi >> 11, s_hi = m_hi & 2047;
#pragma unroll
        for (int nt = 0; nt < 8; nt++) {
            int n = n0 + wn * 64 + nt * 8 + 2 * lq;
            float2 bb = *(const float2*)&bias[n];
            int h = n >> 6, hd = n & 63;
            float2 o0, o1;
            o0.x = (acc[mt][nt][0] + bb.x) * scale;
            o0.y = (acc[mt][nt][1] + bb.y) * scale;
            o1.x = (acc[mt][nt][2] + bb.x) * scale;
            o1.y = (acc[mt][nt][3] + bb.y) * scale;
            *(float2*)&Out[((size_t)(b_lo * NH + h) * NS + s_lo) * NHD + hd] = o0;
            *(float2*)&Out[((size_t)(b_hi * NH + h) * NS + s_hi) * NHD + hd] = o1;
        }
    }
}

// ---------------------------------------------------------------------------
// Pass 1: rowsums of 2^scores. CTA = (bh, q-tile 256), loops 16 k-tiles
// of 128. 8 warps as 4(m) x 2(n); warp tile 64x64. Q in smem once,
// K double-buffered. Writes g_Linv = 1/(16*rowsum).
// ---------------------------------------------------------------------------
#define P1_STRIDE 68
#define P1_QOFF 0
#define P1_KOFF (256 * P1_STRIDE * 4)                 // 69,632
#define P1_RSOFF (P1_KOFF + 2 * 128 * P1_STRIDE * 4)  // 139,264
#define P1_SMEM_TOTAL (P1_RSOFF + 2 * 256 * 4)        // 141,312

__global__ __launch_bounds__(256) void pass1_kernel()
{
    extern __shared__ char smem[];
    float* Qs = (float*)smem;                    // [256][68]
    float* Ks = (float*)(smem + P1_KOFF);        // [2][128][68]
    float* rsb = (float*)(smem + P1_RSOFF);      // [2][256]
    const uint32_t sb_q = smem_u32(Qs);
    const uint32_t sb_k = smem_u32(Ks);

    const int tid = threadIdx.x;
    const int lane = tid & 31, wid = tid >> 5;
    const int lq = lane & 3, lg = lane >> 2;
    const int wm = wid >> 1, wn = wid & 1;
    const int bh = blockIdx.x;
    const int q0 = blockIdx.y * 256;

    auto prefetchK = [&](int st, int kt) {
        int r = tid >> 1, c0 = (tid & 1) * 32;
        uint32_t ks = sb_k + (uint32_t)((st * 128 * P1_STRIDE + r * P1_STRIDE + c0) * 4);
        const float* kg = g_K + ((size_t)bh * NS + kt * 128 + r) * NHD + c0;
#pragma unroll
        for (int i = 0; i < 8; i++) cp16(ks + i * 16, kg + i * 4);
    };

    // Q: 256 rows, 1 thread/row, 16 cp16
    {
        uint32_t qs = sb_q + (uint32_t)(tid * P1_STRIDE * 4);
        const float* qg = g_Q + ((size_t)bh * NS + q0 + tid) * NHD;
#pragma unroll
        for (int i = 0; i < 16; i++) cp16(qs + i * 16, qg + i * 4);
    }
    prefetchK(0, 0);
    CP_COMMIT();

    float rs[4][2];
#pragma unroll
    for (int mt = 0; mt < 4; mt++) { rs[mt][0] = 0.0f; rs[mt][1] = 0.0f; }

    for (int kt = 0; kt < NS / 128; kt++) {
        if (kt + 1 < NS / 128) prefetchK((kt + 1) & 1, kt + 1);
        CP_COMMIT();
        CP_WAIT1();
        __syncthreads();

        const float* Kb = Ks + (kt & 1) * 128 * P1_STRIDE;

        float acc[4][8][4];
#pragma unroll
        for (int mt = 0; mt < 4; mt++)
#pragma unroll
            for (int nt = 0; nt < 8; nt++)
#pragma unroll
                for (int j = 0; j < 4; j++) acc[mt][nt][j] = 0.0f;

#pragma unroll
        for (int s = 0; s < 8; s++) {
            uint32_t a[4][4];
#pragma unroll
            for (int mt = 0; mt < 4; mt++) {
                int r0 = wm * 64 + mt * 16 + lg;
                a[mt][0] = __float_as_uint(Qs[r0 * P1_STRIDE + s * 8 + lq]);
                a[mt][1] = __float_as_uint(Qs[(r0 + 8) * P1_STRIDE + s * 8 + lq]);
                a[mt][2] = __float_as_uint(Qs[r0 * P1_STRIDE + s * 8 + lq + 4]);
                a[mt][3] = __float_as_uint(Qs[(r0 + 8) * P1_STRIDE + s * 8 + lq + 4]);
            }
#pragma unroll
            for (int nt = 0; nt < 8; nt++) {
                int col = wn * 64 + nt * 8 + lg;
                uint32_t b0 = __float_as_uint(Kb[col * P1_STRIDE + s * 8 + lq]);
                uint32_t b1 = __float_as_uint(Kb[col * P1_STRIDE + s * 8 + lq + 4]);
#pragma unroll
                for (int mt = 0; mt < 4; mt++)
                    MMA_TF32(acc[mt][nt], a[mt], b0, b1);
            }
        }

#pragma unroll
        for (int mt = 0; mt < 4; mt++)
#pragma unroll
            for (int nt = 0; nt < 8; nt++) {
                rs[mt][0] += ex2a(acc[mt][nt][0]) + ex2a(acc[mt][nt][1]);
                rs[mt][1] += ex2a(acc[mt][nt][2]) + ex2a(acc[mt][nt][3]);
            }
        __syncthreads();
    }

    // Reduce over lq lanes, stage per-wn, combine, write Linv (with /16 folded)
#pragma unroll
    for (int mt = 0; mt < 4; mt++) {
        rs[mt][0] += __shfl_xor_sync(0xFFFFFFFF, rs[mt][0], 1);
        rs[mt][0] += __shfl_xor_sync(0xFFFFFFFF, rs[mt][0], 2);
        rs[mt][1] += __shfl_xor_sync(0xFFFFFFFF, rs[mt][1], 1);
        rs[mt][1] += __shfl_xor_sync(0xFFFFFFFF, rs[mt][1], 2);
    }
    if (lq == 0) {
#pragma unroll
        for (int mt = 0; mt < 4; mt++) {
            int r = wm * 64 + mt * 16 + lg;
            rsb[wn * 256 + r] = rs[mt][0];
            rsb[wn * 256 + r + 8] = rs[mt][1];
        }
    }
    __syncthreads();
    {
        float tot = rsb[tid] + rsb[256 + tid];
        g_Linv[bh * NS + q0 + tid] = 0.0625f / tot;
    }
}

// ---------------------------------------------------------------------------
// Pass 2: out[b,q,k] = sum_h 2^S_h[q,k] * Linv[bh,q].
// CTA = (k-tile 128, b*16 + q-tile 128); loops 16 heads, Q&K double-buffered.
// 8 warps as 4(m) x 2(n); warp tile 32x64.
// ---------------------------------------------------------------------------
#define P2_STRIDE 68
#define P2_BUF (128 * P2_STRIDE)
#define P2_SMEM_TOTAL (4 * P2_BUF * 4)               // 139,264 B

__global__ __launch_bounds__(256) void pass2_kernel(float* __restrict__ out)
{
    extern __shared__ float p2s[];
    float* Qs = p2s;                      // [2][128][68]
    float* Ks = p2s + 2 * P2_BUF;         // [2][128][68]
    const uint32_t sb_q = smem_u32(Qs);
    const uint32_t sb_k = smem_u32(Ks);

    const int tid = threadIdx.x;
    const int lane = tid & 31, wid = tid >> 5;
    const int lq = lane & 3, lg = lane >> 2;
    const int wm = wid >> 1, wn = wid & 1;
    const int k0 = blockIdx.x * 128;
    const int b = blockIdx.y >> 4;
    const int q0 = (blockIdx.y & 15) * 128;

    auto prefetch = [&](int st, int h) {
        int r = tid >> 1, c0 = (tid & 1) * 32;
        const size_t base = (size_t)(b * NH + h) * NS;
        uint32_t qs = sb_q + (uint32_t)((st * P2_BUF + r * P2_STRIDE + c0) * 4);
        const float* qg = g_Q + (base + q0 + r) * NHD + c0;
#pragma unroll
        for (int i = 0; i < 8; i++) cp16(qs + i * 16, qg + i * 4);
        uint32_t ks = sb_k + (uint32_t)((st * P2_BUF + r * P2_STRIDE + c0) * 4);
        const float* kg = g_K + (base + k0 + r) * NHD + c0;
#pragma unroll
        for (int i = 0; i < 8; i++) cp16(ks + i * 16, kg + i * 4);
    };

    float oacc[2][8][4];
#pragma unroll
    for (int mt = 0; mt < 2; mt++)
#pragma unroll
        for (int nt = 0; nt < 8; nt++)
#pragma unroll
            for (int j = 0; j < 4; j++) oacc[mt][nt][j] = 0.0f;

    prefetch(0, 0);
    CP_COMMIT();

    for (int h = 0; h < NH; h++) {
        if (h + 1 < NH) prefetch((h + 1) & 1, h + 1);
        CP_COMMIT();
        CP_WAIT1();
        __syncthreads();

        const float* Qb = Qs + (h & 1) * P2_BUF;
        const float* Kb = Ks + (h & 1) * P2_BUF;

        float w[2][2];
#pragma unroll
        for (int mt = 0; mt < 2; mt++) {
            int r = q0 + wm * 32 + mt * 16 + lg;
            w[mt][0] = g_Linv[(b * NH + h) * NS + r];
            w[mt][1] = g_Linv[(b * NH + h) * NS + r + 8];
        }

        float acc[2][8][4];
#pragma unroll
        for (int mt = 0; mt < 2; mt++)
#pragma unroll
            for (int nt = 0; nt < 8; nt++)
#pragma unroll
                for (int j = 0; j < 4; j++) acc[mt][nt][j] = 0.0f;

#pragma unroll
        for (int s = 0; s < 8; s++) {
            uint32_t a[2][4];
#pragma unroll
            for (int mt = 0; mt < 2; mt++) {
                int r0 = wm * 32 + mt * 16 + lg;
                a[mt][0] = __float_as_uint(Qb[r0 * P2_STRIDE + s * 8 + lq]);
                a[mt][1] = __float_as_uint(Qb[(r0 + 8) * P2_STRIDE + s * 8 + lq]);
                a[mt][2] = __float_as_uint(Qb[r0 * P2_STRIDE + s * 8 + lq + 4]);
                a[mt][3] = __float_as_uint(Qb[(r0 + 8) * P2_STRIDE + s * 8 + lq + 4]);
            }
#pragma unroll
            for (int nt = 0; nt < 8; nt++) {
                int col = wn * 64 + nt * 8 + lg;
                uint32_t b0 = __float_as_uint(Kb[col * P2_STRIDE + s * 8 + lq]);
                uint32_t b1 = __float_as_uint(Kb[col * P2_STRIDE + s * 8 + lq + 4]);
#pragma unroll
                for (int mt = 0; mt < 2; mt++)
                    MMA_TF32(acc[mt][nt], a[mt], b0, b1);
            }
        }

#pragma unroll
        for (int mt = 0; mt < 2; mt++)
#pragma unroll
            for (int nt = 0; nt < 8; nt++) {
                oacc[mt][nt][0] += ex2a(acc[mt][nt][0]) * w[mt][0];
                oacc[mt][nt][1] += ex2a(acc[mt][nt][1]) * w[mt][0];
                oacc[mt][nt][2] += ex2a(acc[mt][nt][2]) * w[mt][1];
                oacc[mt][nt][3] += ex2a(acc[mt][nt][3]) * w[mt][1];
            }
        __syncthreads();
    }

    // Write output tile
#pragma unroll
    for (int mt = 0; mt < 2; mt++) {
        int r_lo = q0 + wm * 32 + mt * 16 + lg;
        int r_hi = r_lo + 8;
#pragma unroll
        for (int nt = 0; nt < 8; nt++) {
            int c = k0 + wn * 64 + nt * 8 + 2 * lq;
            *(float2*)&out[((size_t)b * NS + r_lo) * NS + c] =
                make_float2(oacc[mt][nt][0], oacc[mt][nt][1]);
            *(float2*)&out[((size_t)b * NS + r_hi) * NS + c] =
                make_float2(oacc[mt][nt][2], oacc[mt][nt][3]);
        }
    }
}

// ---------------------------------------------------------------------------
extern "C" void kernel_launch(void* const* d_in, const int* in_sizes, int n_in,
                              void* d_out, int out_size)
{
    const float* query = (const float*)d_in[0];
    const float* key   = (const float*)d_in[1];
    const float* Wq    = (const float*)d_in[2];
    const float* bq    = (const float*)d_in[3];
    const float* Wk    = (const float*)d_in[4];
    const float* bk    = (const float*)d_in[5];
    float* out = (float*)d_out;

    cudaFuncSetAttribute(proj_kernel,
                         cudaFuncAttributeMaxDynamicSharedMemorySize,
                         PJ_SMEM_TOTAL);
    cudaFuncSetAttribute(pass1_kernel,
                         cudaFuncAttributeMaxDynamicSharedMemorySize,
                         P1_SMEM_TOTAL);
    cudaFuncSetAttribute(pass2_kernel,
                         cudaFuncAttributeMaxDynamicSharedMemorySize,
                         P2_SMEM_TOTAL);

    proj_kernel<<<dim3(ND / 128, (NB * NS) / 256, 2), 256, PJ_SMEM_TOTAL>>>(
        query, key, Wq, bq, Wk, bk);
    pass1_kernel<<<dim3(NB * NH, NS / 256), 256, P1_SMEM_TOTAL>>>();
    pass2_kernel<<<dim3(NS / 128, NB * (NS / 128)), 256, P2_SMEM_TOTAL>>>(out);
}